// round 7
// baseline (speedup 1.0000x reference)
#include <cuda_runtime.h>
#include <cuda_bf16.h>
#include <cstdint>

// ---------------- problem constants ----------------
#define BB 512
#define DD 512
#define CC 100000
#define S_SCALE 30.0f
#define COS_M 0.8775825618903728f
#define SIN_M 0.479425538604203f
#define TH_   (-0.8775825618903728f)
#define MM_   0.2397127693021015f

// ---------------- scratch (device globals, no allocs) ----------------
__device__ float g_xinv[BB];
__device__ float g_winv[CC];
__device__ int   g_label[BB];
__device__ float g_xt[BB * DD];            // tf32-rounded x
__device__ float g_wt[(size_t)CC * DD];    // tf32-rounded w

// ---------------- helpers ----------------
__device__ __forceinline__ uint32_t smem_u32(const void* p) {
    uint32_t a;
    asm("{ .reg .u64 t; cvta.to.shared.u64 t, %1; cvt.u32.u64 %0, t; }" : "=r"(a) : "l"(p));
    return a;
}
__device__ __forceinline__ void ldsm_x4(uint32_t* r, uint32_t addr) {
    asm volatile("ldmatrix.sync.aligned.m8n8.x4.shared.b16 {%0,%1,%2,%3}, [%4];"
                 : "=r"(r[0]), "=r"(r[1]), "=r"(r[2]), "=r"(r[3]) : "r"(addr));
}
__device__ __forceinline__ void mma1688(float* d, const uint32_t* a, const uint32_t* b) {
    asm volatile("mma.sync.aligned.m16n8k8.row.col.f32.tf32.tf32.f32 "
                 "{%0,%1,%2,%3}, {%4,%5,%6,%7}, {%8,%9}, {%0,%1,%2,%3};"
                 : "+f"(d[0]), "+f"(d[1]), "+f"(d[2]), "+f"(d[3])
                 : "r"(a[0]), "r"(a[1]), "r"(a[2]), "r"(a[3]), "r"(b[0]), "r"(b[1]));
}
__device__ __forceinline__ void cp16(uint32_t dst, const void* src, int src_sz) {
    asm volatile("cp.async.cg.shared.global [%0], [%1], 16, %2;"
                 :: "r"(dst), "l"(src), "r"(src_sz) : "memory");
}
#define CP_COMMIT() asm volatile("cp.async.commit_group;" ::: "memory")
#define CP_WAIT0()  asm volatile("cp.async.wait_group 0;" ::: "memory")

// round-to-nearest fp32 -> tf32 (kept in fp32 container)
__device__ __forceinline__ float tf32r(float a) {
    uint32_t r;
    asm("cvt.rna.tf32.f32 %0, %1;" : "=r"(r) : "f"(a));
    return __uint_as_float(r);
}

// ---------------- label dtype normalization (int64-delivered-as-int32 safe) ----------------
__global__ void label_fix_kernel(const int* __restrict__ p) {
    __shared__ int is64;
    if (threadIdx.x == 0) is64 = 1;
    __syncthreads();
    if (threadIdx.x < 64) {
        if (p[2 * threadIdx.x + 1] != 0) is64 = 0;  // benign race: only writes 0
    }
    __syncthreads();
    int i = threadIdx.x;
    if (i < BB) g_label[i] = is64 ? p[2 * i] : p[i];
}

// ---------------- fused tf32-round + inverse-row-norm, 1 warp/row ----------------
__device__ __forceinline__ void cvt_norm_body(const float* __restrict__ src,
                                              float* __restrict__ dt,
                                              float* __restrict__ dinv, int nrows) {
    int warp = (blockIdx.x * blockDim.x + threadIdx.x) >> 5;
    int lane = threadIdx.x & 31;
    if (warp >= nrows) return;
    const float4* p = (const float4*)(src + (size_t)warp * DD);
    float ss = 0.f;
#pragma unroll
    for (int i = 0; i < 4; i++) {
        float4 v = p[lane + i * 32];
        ss += v.x * v.x + v.y * v.y + v.z * v.z + v.w * v.w;   // norm from ORIGINAL fp32
        float4 t;
        t.x = tf32r(v.x); t.y = tf32r(v.y);
        t.z = tf32r(v.z); t.w = tf32r(v.w);
        *(float4*)(dt + (size_t)warp * DD + (size_t)(lane + i * 32) * 4) = t;
    }
#pragma unroll
    for (int o = 16; o; o >>= 1) ss += __shfl_xor_sync(0xFFFFFFFFu, ss, o);
    if (lane == 0) dinv[warp] = 1.0f / fmaxf(sqrtf(ss), 1e-12f);
}
__global__ void xcvt_kernel(const float* __restrict__ x) { cvt_norm_body(x, g_xt, g_xinv, BB); }
__global__ void wcvt_kernel(const float* __restrict__ w) { cvt_norm_body(w, g_wt, g_winv, CC); }

// ---------------- GEMM + ArcFace epilogue ----------------
// CTA 256 thr, tile 128x128, K chunks of 64 fp32/tf32 (8 iters, 8 k8 steps).
// Double-buffered smem + DOUBLE-BUFFERED REGISTER FRAGMENTS, warp tile 64x32.
#define KC 64
#define N_ITERS (DD / KC)       // 8
#define OFF_A 0                 // 128 rows x 64 fp32 = 32 KB
#define OFF_B 32768
#define BUF_B 65536
#define S_WINV (2 * BUF_B)              // 131072
#define S_XINV (S_WINV + 512)
#define SMEM_TOTAL (S_XINV + 512)       // 132096

// byte offset of 16B chunk (row, chunk 0..15) in a [128][64 fp32] tile, XOR-swizzled
__device__ __forceinline__ uint32_t swz16(int row, int ch) {
    return (uint32_t)(row * 256 + ((ch ^ (row & 7)) << 4));
}

__global__ void __launch_bounds__(256, 1)
arcface_gemm(float* __restrict__ out) {
    extern __shared__ __align__(1024) char smem[];
    const uint32_t sb = smem_u32(smem);
    const int tid = threadIdx.x;
    const int lane = tid & 31;
    const int wid = tid >> 5;
    const int wrow = wid >> 2;   // 0..1
    const int wcol = wid & 3;    // 0..3
    const int tm = blockIdx.x;   // 0..3 (fastest -> weight-tile L2 reuse)
    const int tn = blockIdx.y;   // 0..781

    // stage norm tiles
    if (tid < 128) {
        int c = tn * 128 + tid;
        *(float*)(smem + S_WINV + tid * 4) = (c < CC) ? g_winv[c] : 1.0f;
        *(float*)(smem + S_XINV + tid * 4) = g_xinv[tm * 128 + tid];
    }

    // cp.async of one K-chunk (A 32KB + B 32KB) into buffer at byte offset boff
    auto issue = [&](uint32_t boff, int it) {
#pragma unroll
        for (int i = 0; i < 8; i++) {
            int idx = tid + i * 256;      // 0..2047
            int row = idx >> 4;
            int ch = idx & 15;            // 16B chunk = 4 fp32
            uint32_t so = swz16(row, ch);
            size_t asrc = (size_t)(tm * 128 + row) * DD + it * KC + ch * 4;
            cp16(sb + boff + OFF_A + so, &g_xt[asrc], 16);
            int gr = tn * 128 + row;
            int ok = gr < CC;
            size_t bsrc = (size_t)(ok ? gr : 0) * DD + it * KC + ch * 4;
            cp16(sb + boff + OFF_B + so, &g_wt[bsrc], ok ? 16 : 0);  // zero-fill OOB
        }
        CP_COMMIT();
    };

    const int q = lane >> 3, rr = lane & 7;   // ldsm lane-group decomposition
    const int arow = wrow * 64 + rr + (q & 1) * 8;   // A ldsm row base, ch += (q>>1)
    const int bn   = wcol * 32 + rr + (q >> 1) * 8;  // B ldsm n base,  ch += (q&1)

    // fragment loader for one k8 step into slot s
    uint32_t ah[2][4][4], bf[2][2][4];
    auto load_frags = [&](int s, uint32_t cur, int ks) {
        int cha = 2 * ks + (q >> 1);
#pragma unroll
        for (int mt = 0; mt < 4; mt++)
            ldsm_x4(ah[s][mt], sb + cur + OFF_A + swz16(arow + mt * 16, cha));
        int chb = 2 * ks + (q & 1);
#pragma unroll
        for (int np = 0; np < 2; np++)
            ldsm_x4(bf[s][np], sb + cur + OFF_B + swz16(bn + np * 16, chb));
    };

    float acc[4][4][4];
#pragma unroll
    for (int a = 0; a < 4; a++)
#pragma unroll
        for (int b = 0; b < 4; b++)
#pragma unroll
            for (int c = 0; c < 4; c++) acc[a][b][c] = 0.f;

    issue(0, 0);
    uint32_t cur = 0;
    CP_WAIT0();
    __syncthreads();
    load_frags(0, cur, 0);

#pragma unroll 1
    for (int it = 0; it < N_ITERS; it++) {
        if (it + 1 < N_ITERS) issue(cur ^ BUF_B, it + 1);

#pragma unroll
        for (int ks = 0; ks < 8; ks++) {
            int s = ks & 1;
            if (ks < 7) load_frags(s ^ 1, cur, ks + 1);   // prefetch next step's frags
#pragma unroll
            for (int mt = 0; mt < 4; mt++)
#pragma unroll
                for (int nt = 0; nt < 4; nt++)
                    mma1688(acc[mt][nt], ah[s][mt], &bf[s][nt >> 1][(nt & 1) * 2]);
        }
        cur ^= BUF_B;
        if (it + 1 < N_ITERS) {
            CP_WAIT0();
            __syncthreads();
            load_frags(0, cur, 0);
        }
    }

    // ---------------- epilogue ----------------
    const int gr = lane >> 2;
    const int gc = (lane & 3) * 2;
    const float* winv_s = (const float*)(smem + S_WINV);
    const float* xinv_s = (const float*)(smem + S_XINV);

#pragma unroll
    for (int mt = 0; mt < 4; mt++) {
        int lm0 = wrow * 64 + mt * 16 + gr;
        int lm1 = lm0 + 8;
        int gm0 = tm * 128 + lm0, gm1 = gm0 + 8;
        float xi0 = xinv_s[lm0], xi1 = xinv_s[lm1];
        int lab0 = g_label[gm0], lab1 = g_label[gm1];
#pragma unroll
        for (int nt = 0; nt < 4; nt++) {
            int lc = wcol * 32 + nt * 8 + gc;
            int col = tn * 128 + lc;
            if (col < CC) {
                float wv0 = winv_s[lc], wv1 = winv_s[lc + 1];
                float2 o0, o1;
                {
                    float c0 = acc[mt][nt][0] * xi0 * wv0;
                    float c1 = acc[mt][nt][1] * xi0 * wv1;
                    o0.x = S_SCALE * c0; o0.y = S_SCALE * c1;
                    if (lab0 == col) {
                        float s = sqrtf(fmaxf(1.f - c0 * c0, 0.f));
                        float phi = c0 * COS_M - s * SIN_M;
                        o0.x = S_SCALE * ((c0 > TH_) ? phi : (c0 - MM_));
                    }
                    if (lab0 == col + 1) {
                        float s = sqrtf(fmaxf(1.f - c1 * c1, 0.f));
                        float phi = c1 * COS_M - s * SIN_M;
                        o0.y = S_SCALE * ((c1 > TH_) ? phi : (c1 - MM_));
                    }
                }
                {
                    float c2 = acc[mt][nt][2] * xi1 * wv0;
                    float c3 = acc[mt][nt][3] * xi1 * wv1;
                    o1.x = S_SCALE * c2; o1.y = S_SCALE * c3;
                    if (lab1 == col) {
                        float s = sqrtf(fmaxf(1.f - c2 * c2, 0.f));
                        float phi = c2 * COS_M - s * SIN_M;
                        o1.x = S_SCALE * ((c2 > TH_) ? phi : (c2 - MM_));
                    }
                    if (lab1 == col + 1) {
                        float s = sqrtf(fmaxf(1.f - c3 * c3, 0.f));
                        float phi = c3 * COS_M - s * SIN_M;
                        o1.y = S_SCALE * ((c3 > TH_) ? phi : (c3 - MM_));
                    }
                }
                *(float2*)(out + (size_t)gm0 * CC + col) = o0;
                *(float2*)(out + (size_t)gm1 * CC + col) = o1;
            }
        }
    }
}

// ---------------- launch ----------------
extern "C" void kernel_launch(void* const* d_in, const int* in_sizes, int n_in,
                              void* d_out, int out_size) {
    const float* x = (const float*)d_in[0];
    const float* w = (const float*)d_in[1];
    const int* labraw = (const int*)d_in[2];
    float* out = (float*)d_out;

    label_fix_kernel<<<1, 512>>>(labraw);
    xcvt_kernel<<<(BB * 32 + 255) / 256, 256>>>(x);
    wcvt_kernel<<<(CC * 32 + 255) / 256, 256>>>(w);

    cudaFuncSetAttribute(arcface_gemm, cudaFuncAttributeMaxDynamicSharedMemorySize, SMEM_TOTAL);
    dim3 grid(BB / 128, (CC + 127) / 128);  // (4, 782)
    arcface_gemm<<<grid, 256, SMEM_TOTAL>>>(out);
}

// round 8
// speedup vs baseline: 1.5038x; 1.5038x over previous
#include <cuda_runtime.h>
#include <cuda_fp16.h>
#include <cstdint>

// ---------------- problem constants ----------------
#define BB 512
#define DD 512
#define CC 100000
#define S_SCALE 30.0f
#define COS_M 0.8775825618903728f
#define SIN_M 0.479425538604203f
#define TH_   (-0.8775825618903728f)
#define MM_   0.2397127693021015f

// ---------------- scratch (device globals, no allocs) ----------------
__device__ float g_xinv[BB];
__device__ float g_winv[CC];
__device__ int   g_label[BB];
__device__ __half g_xh[BB * DD];            // fp16 x
__device__ __half g_wh[(size_t)CC * DD];    // fp16 w

// ---------------- helpers ----------------
__device__ __forceinline__ uint32_t smem_u32(const void* p) {
    uint32_t a;
    asm("{ .reg .u64 t; cvta.to.shared.u64 t, %1; cvt.u32.u64 %0, t; }" : "=r"(a) : "l"(p));
    return a;
}
__device__ __forceinline__ void ldsm_x4(uint32_t* r, uint32_t addr) {
    asm volatile("ldmatrix.sync.aligned.m8n8.x4.shared.b16 {%0,%1,%2,%3}, [%4];"
                 : "=r"(r[0]), "=r"(r[1]), "=r"(r[2]), "=r"(r[3]) : "r"(addr));
}
__device__ __forceinline__ void mma16816(float* d, const uint32_t* a, const uint32_t* b) {
    asm volatile("mma.sync.aligned.m16n8k16.row.col.f32.f16.f16.f32 "
                 "{%0,%1,%2,%3}, {%4,%5,%6,%7}, {%8,%9}, {%0,%1,%2,%3};"
                 : "+f"(d[0]), "+f"(d[1]), "+f"(d[2]), "+f"(d[3])
                 : "r"(a[0]), "r"(a[1]), "r"(a[2]), "r"(a[3]), "r"(b[0]), "r"(b[1]));
}
__device__ __forceinline__ void cp16(uint32_t dst, const void* src, int src_sz) {
    asm volatile("cp.async.cg.shared.global [%0], [%1], 16, %2;"
                 :: "r"(dst), "l"(src), "r"(src_sz) : "memory");
}
#define CP_COMMIT() asm volatile("cp.async.commit_group;" ::: "memory")
#define CP_WAIT(n)  asm volatile("cp.async.wait_group %0;" :: "n"(n) : "memory")

// ---------------- label dtype normalization (int64-delivered-as-int32 safe) ----------------
__global__ void label_fix_kernel(const int* __restrict__ p) {
    __shared__ int is64;
    if (threadIdx.x == 0) is64 = 1;
    __syncthreads();
    if (threadIdx.x < 64) {
        if (p[2 * threadIdx.x + 1] != 0) is64 = 0;  // benign race: only writes 0
    }
    __syncthreads();
    int i = threadIdx.x;
    if (i < BB) g_label[i] = is64 ? p[2 * i] : p[i];
}

// ---------------- fused fp16-convert + inverse-row-norm, 1 warp/row ----------------
__device__ __forceinline__ void cvt_norm_body(const float* __restrict__ src,
                                              __half* __restrict__ dh,
                                              float* __restrict__ dinv, int nrows) {
    int warp = (blockIdx.x * blockDim.x + threadIdx.x) >> 5;
    int lane = threadIdx.x & 31;
    if (warp >= nrows) return;
    const float4* p = (const float4*)(src + (size_t)warp * DD);
    float ss = 0.f;
#pragma unroll
    for (int i = 0; i < 4; i++) {
        float4 v = p[lane + i * 32];
        ss += v.x * v.x + v.y * v.y + v.z * v.z + v.w * v.w;   // norm from ORIGINAL fp32
        __half2 h0 = __floats2half2_rn(v.x, v.y);
        __half2 h1 = __floats2half2_rn(v.z, v.w);
        uint2 pk;
        pk.x = *reinterpret_cast<uint32_t*>(&h0);
        pk.y = *reinterpret_cast<uint32_t*>(&h1);
        *(uint2*)(dh + (size_t)warp * DD + (size_t)(lane + i * 32) * 4) = pk;
    }
#pragma unroll
    for (int o = 16; o; o >>= 1) ss += __shfl_xor_sync(0xFFFFFFFFu, ss, o);
    if (lane == 0) dinv[warp] = 1.0f / fmaxf(sqrtf(ss), 1e-12f);
}
__global__ void xcvt_kernel(const float* __restrict__ x) { cvt_norm_body(x, g_xh, g_xinv, BB); }
__global__ void wcvt_kernel(const float* __restrict__ w) { cvt_norm_body(w, g_wh, g_winv, CC); }

// ---------------- GEMM + ArcFace epilogue ----------------
// CTA 256 thr, tile 128x128, K chunks of 64 fp16 (8 iters, 4 k16 steps each).
// 4-stage cp.async pipeline (wait_group 2), warp tile 64x32, mma m16n8k16 f16.
#define KC 64
#define N_ITERS (DD / KC)       // 8
#define NSTAGE 4
#define OFF_A 0                 // 128 rows x 64 fp16 = 16 KB
#define OFF_B 16384
#define STAGE_B 32768
#define S_WINV (NSTAGE * STAGE_B)       // 131072
#define S_XINV (S_WINV + 512)
#define SMEM_TOTAL (S_XINV + 512)       // 132096

// byte offset of 16B chunk (row, chunk 0..7) in a [128][64 fp16] tile, XOR-swizzled
__device__ __forceinline__ uint32_t swz64(int row, int ch) {
    return (uint32_t)(row * 128 + ((ch ^ (row & 7)) << 4));
}

__global__ void __launch_bounds__(256, 1)
arcface_gemm(float* __restrict__ out) {
    extern __shared__ __align__(1024) char smem[];
    const uint32_t sb = smem_u32(smem);
    const int tid = threadIdx.x;
    const int lane = tid & 31;
    const int wid = tid >> 5;
    const int wrow = wid >> 2;   // 0..1
    const int wcol = wid & 3;    // 0..3
    const int tm = blockIdx.x;   // 0..3 (fastest -> weight-tile L2 reuse)
    const int tn = blockIdx.y;   // 0..781

    // stage norm tiles
    if (tid < 128) {
        int c = tn * 128 + tid;
        *(float*)(smem + S_WINV + tid * 4) = (c < CC) ? g_winv[c] : 1.0f;
        *(float*)(smem + S_XINV + tid * 4) = g_xinv[tm * 128 + tid];
    }

    // cp.async of one K-chunk (A 16KB + B 16KB) into stage s
    auto issue = [&](int s, int it) {
        uint32_t boff = (uint32_t)s * STAGE_B;
#pragma unroll
        for (int i = 0; i < 4; i++) {
            int idx = tid + i * 256;      // 0..1023
            int row = idx >> 3;
            int ch = idx & 7;             // 16B chunk = 8 fp16
            uint32_t so = swz64(row, ch);
            size_t asrc = (size_t)(tm * 128 + row) * DD + it * KC + ch * 8;
            cp16(sb + boff + OFF_A + so, &g_xh[asrc], 16);
            int gr = tn * 128 + row;
            int ok = gr < CC;
            size_t bsrc = (size_t)(ok ? gr : 0) * DD + it * KC + ch * 8;
            cp16(sb + boff + OFF_B + so, &g_wh[bsrc], ok ? 16 : 0);  // zero-fill OOB
        }
        CP_COMMIT();
    };

    float acc[4][4][4];
#pragma unroll
    for (int a = 0; a < 4; a++)
#pragma unroll
        for (int b = 0; b < 4; b++)
#pragma unroll
            for (int c = 0; c < 4; c++) acc[a][b][c] = 0.f;

    // prologue: fill 3 stages
    issue(0, 0);
    issue(1, 1);
    issue(2, 2);

    const int r16 = lane & 15, kc = lane >> 4;        // A ldsm pattern
    const int q = lane >> 3, rr = lane & 7;           // B ldsm pattern

#pragma unroll 1
    for (int it = 0; it < N_ITERS; it++) {
        CP_WAIT(2);          // stage `it` complete (<=2 groups pending)
        __syncthreads();     // visibility + buffer-reuse safety
        if (it + 3 < N_ITERS) issue((it + 3) & 3, it + 3);
        uint32_t cur = sb + (uint32_t)(it & 3) * STAGE_B;

#pragma unroll
        for (int ks = 0; ks < 4; ks++) {
            uint32_t ah[4][4], bh[2][4];
#pragma unroll
            for (int mt = 0; mt < 4; mt++) {
                int row = wrow * 64 + mt * 16 + r16;
                ldsm_x4(ah[mt], cur + OFF_A + swz64(row, ks * 2 + kc));
            }
#pragma unroll
            for (int np = 0; np < 2; np++) {
                int n = wcol * 32 + np * 16 + (q >> 1) * 8 + rr;
                ldsm_x4(bh[np], cur + OFF_B + swz64(n, ks * 2 + (q & 1)));
            }
#pragma unroll
            for (int mt = 0; mt < 4; mt++)
#pragma unroll
                for (int nt = 0; nt < 4; nt++)
                    mma16816(acc[mt][nt], ah[mt], &bh[nt >> 1][(nt & 1) * 2]);
        }
    }

    // ---------------- epilogue ----------------
    const int gr = lane >> 2;
    const int gc = (lane & 3) * 2;
    const float* winv_s = (const float*)(smem + S_WINV);
    const float* xinv_s = (const float*)(smem + S_XINV);

#pragma unroll
    for (int mt = 0; mt < 4; mt++) {
        int lm0 = wrow * 64 + mt * 16 + gr;
        int lm1 = lm0 + 8;
        int gm0 = tm * 128 + lm0, gm1 = gm0 + 8;
        float xi0 = xinv_s[lm0], xi1 = xinv_s[lm1];
        int lab0 = g_label[gm0], lab1 = g_label[gm1];
#pragma unroll
        for (int nt = 0; nt < 4; nt++) {
            int lc = wcol * 32 + nt * 8 + gc;
            int col = tn * 128 + lc;
            if (col < CC) {
                float wv0 = winv_s[lc], wv1 = winv_s[lc + 1];
                float2 o0, o1;
                {
                    float c0 = acc[mt][nt][0] * xi0 * wv0;
                    float c1 = acc[mt][nt][1] * xi0 * wv1;
                    o0.x = S_SCALE * c0; o0.y = S_SCALE * c1;
                    if (lab0 == col) {
                        float s = sqrtf(fmaxf(1.f - c0 * c0, 0.f));
                        float phi = c0 * COS_M - s * SIN_M;
                        o0.x = S_SCALE * ((c0 > TH_) ? phi : (c0 - MM_));
                    }
                    if (lab0 == col + 1) {
                        float s = sqrtf(fmaxf(1.f - c1 * c1, 0.f));
                        float phi = c1 * COS_M - s * SIN_M;
                        o0.y = S_SCALE * ((c1 > TH_) ? phi : (c1 - MM_));
                    }
                }
                {
                    float c2 = acc[mt][nt][2] * xi1 * wv0;
                    float c3 = acc[mt][nt][3] * xi1 * wv1;
                    o1.x = S_SCALE * c2; o1.y = S_SCALE * c3;
                    if (lab1 == col) {
                        float s = sqrtf(fmaxf(1.f - c2 * c2, 0.f));
                        float phi = c2 * COS_M - s * SIN_M;
                        o1.x = S_SCALE * ((c2 > TH_) ? phi : (c2 - MM_));
                    }
                    if (lab1 == col + 1) {
                        float s = sqrtf(fmaxf(1.f - c3 * c3, 0.f));
                        float phi = c3 * COS_M - s * SIN_M;
                        o1.y = S_SCALE * ((c3 > TH_) ? phi : (c3 - MM_));
                    }
                }
                *(float2*)(out + (size_t)gm0 * CC + col) = o0;
                *(float2*)(out + (size_t)gm1 * CC + col) = o1;
            }
        }
    }
}

// ---------------- launch ----------------
extern "C" void kernel_launch(void* const* d_in, const int* in_sizes, int n_in,
                              void* d_out, int out_size) {
    const float* x = (const float*)d_in[0];
    const float* w = (const float*)d_in[1];
    const int* labraw = (const int*)d_in[2];
    float* out = (float*)d_out;

    label_fix_kernel<<<1, 512>>>(labraw);
    xcvt_kernel<<<(BB * 32 + 255) / 256, 256>>>(x);
    wcvt_kernel<<<(CC * 32 + 255) / 256, 256>>>(w);

    cudaFuncSetAttribute(arcface_gemm, cudaFuncAttributeMaxDynamicSharedMemorySize, SMEM_TOTAL);
    dim3 grid(BB / 128, (CC + 127) / 128);  // (4, 782)
    arcface_gemm<<<grid, 256, SMEM_TOTAL>>>(out);
}